// round 1
// baseline (speedup 1.0000x reference)
#include <cuda_runtime.h>
#include <cuda_bf16.h>
#include <math.h>

// Problem constants (fixed by the dataset)
#define BB 2048
#define KK 64
#define CC 3
#define EE 16
#define DIN 768            // C*E*E
#define CF 64
#define MROWS (BB*KK)      // 131072
#define SHARPNESS 1048576.0f   // CF * E*E*E * 4

// ---------------- scratch (no allocations allowed) ----------------
__device__ float g_WphiT[DIN*CF];       // Wphi transposed [k][f]
__device__ float g_xfeat[BB*CF];        // normalized x features
__device__ float g_scores[MROWS];       // scores[b*K+k]
__device__ float g_weights[MROWS];      // softmax weights
__device__ float g_sw[BB];              // switch per b

// ---------------- helpers ----------------
__device__ __forceinline__ void cpa16(void* smem, const void* g) {
    unsigned s = (unsigned)__cvta_generic_to_shared(smem);
    asm volatile("cp.async.cg.shared.global [%0], [%1], 16;" :: "r"(s), "l"(g));
}
#define CP_COMMIT() asm volatile("cp.async.commit_group;")
#define CP_WAIT1()  asm volatile("cp.async.wait_group 1;")

__device__ __forceinline__ unsigned long long pk2(float a, float b) {
    unsigned long long r;
    asm("mov.b64 %0, {%1, %2};" : "=l"(r) : "f"(a), "f"(b));
    return r;
}
__device__ __forceinline__ void fma2(unsigned long long& d, unsigned long long a, unsigned long long b) {
    asm("fma.rn.f32x2 %0, %1, %2, %0;" : "+l"(d) : "l"(a), "l"(b));
}
__device__ __forceinline__ void upk2(unsigned long long v, float& a, float& b) {
    asm("mov.b64 {%0, %1}, %2;" : "=f"(a), "=f"(b) : "l"(v));
}

// ---------------- kernel E: transpose Wphi [64][768] -> [768][64] ----------------
__global__ void kernE(const float* __restrict__ Wphi) {
    int o = blockIdx.x * 256 + threadIdx.x;   // o = k*64 + f
    int k = o >> 6, f = o & 63;
    g_WphiT[o] = Wphi[f * DIN + k];
}

// ---------------- kernel A: x_feat = l2norm(x_im @ Wtheta^T + btheta) ----------------
// 8 batch rows per block, 256 threads: f = tid&63, group g = tid>>6 handles b 2g,2g+1
__global__ void __launch_bounds__(256) kernA(const float* __restrict__ xim,
                                             const float* __restrict__ Wtheta,
                                             const float* __restrict__ btheta) {
    __shared__ __align__(16) float xs[8 * DIN];      // 24KB
    __shared__ float wred[8][2];
    int tid = threadIdx.x;
    int b0 = blockIdx.x * 8;

    const float4* src = (const float4*)(xim + (size_t)b0 * DIN);
    float4* d4 = (float4*)xs;
#pragma unroll
    for (int j = 0; j < 6; j++) d4[tid + 256 * j] = src[tid + 256 * j];
    __syncthreads();

    int f = tid & 63, g = tid >> 6;
    const float* wr = Wtheta + (size_t)f * DIN;
    const float* xa = xs + (2 * g) * DIN;
    const float* xb = xs + (2 * g + 1) * DIN;
    float a0 = 0.f, a1 = 0.f;
    for (int i = 0; i < DIN; i += 4) {
        float4 w4 = *(const float4*)(wr + i);
        float4 va = *(const float4*)(xa + i);
        float4 vb = *(const float4*)(xb + i);
        a0 += w4.x * va.x + w4.y * va.y + w4.z * va.z + w4.w * va.w;
        a1 += w4.x * vb.x + w4.y * vb.y + w4.z * vb.z + w4.w * vb.w;
    }
    a0 += btheta[f];
    a1 += btheta[f];

    float s0 = a0 * a0, s1 = a1 * a1;
#pragma unroll
    for (int o = 1; o < 32; o <<= 1) {
        s0 += __shfl_xor_sync(0xffffffffu, s0, o);
        s1 += __shfl_xor_sync(0xffffffffu, s1, o);
    }
    int w = tid >> 5;
    if ((tid & 31) == 0) { wred[w][0] = s0; wred[w][1] = s1; }
    __syncthreads();
    int wb = g << 1;
    float n0 = wred[wb][0] + wred[wb + 1][0];
    float n1 = wred[wb][1] + wred[wb + 1][1];
    g_xfeat[(b0 + 2 * g) * CF + f]     = a0 / fmaxf(sqrtf(n0), 1e-12f);
    g_xfeat[(b0 + 2 * g + 1) * CF + f] = a1 / fmaxf(sqrtf(n1), 1e-12f);
}

// ---------------- kernel B: scores GEMM (the big one) ----------------
// Tile: 128 rows x 64 feats, k-chunk 16, cp.async double buffered, FFMA2.
// Thread (ty=tid>>3, tx=tid&7): rows ty+32r (r=0..3), feats 8*tx..8*tx+7 (4 f32x2 pairs).
#define ASTR 20     // A smem row stride (floats): keeps 16B cp.async alignment, conflict-free LDS
__global__ void __launch_bounds__(256) kernB(const float* __restrict__ pim,
                                             const float* __restrict__ bphi) {
    __shared__ __align__(16) float Asm[2][128 * ASTR];   // 20KB
    __shared__ __align__(16) float Wsm[2][16 * 64];      // 8KB
    __shared__ float xfsm[128];
    __shared__ float bpsm[64];

    const int tid = threadIdx.x;
    const int m0 = blockIdx.x * 128;
    if (tid < 128) xfsm[tid] = g_xfeat[m0 + tid];   // b0*64..b0*64+127 == m0..m0+127
    if (tid < 64)  bpsm[tid] = bphi[tid];

    const int ty = tid >> 3, tx = tid & 7, f0 = tx * 8;
    unsigned long long acc[4][4];
#pragma unroll
    for (int r = 0; r < 4; r++)
#pragma unroll
        for (int fp = 0; fp < 4; fp++) acc[r][fp] = 0ull;

    const int arow = tid >> 2;
    const int aseg = (tid & 3) * 4;
    const int wk   = tid >> 4;
    const int wf4  = (tid & 15) * 4;

    auto issue = [&](int c, int s) {
#pragma unroll
        for (int j = 0; j < 2; j++) {
            int row = arow + 64 * j;
            cpa16(&Asm[s][row * ASTR + aseg],
                  pim + (size_t)(m0 + row) * DIN + c * 16 + aseg);
        }
        cpa16(&Wsm[s][wk * 64 + wf4], g_WphiT + (size_t)(c * 16 + wk) * 64 + wf4);
    };

    issue(0, 0); CP_COMMIT();
    issue(1, 1); CP_COMMIT();

    for (int c = 0; c < 48; c++) {
        const int s = c & 1;
        CP_WAIT1();
        __syncthreads();
#pragma unroll
        for (int kk = 0; kk < 16; kk++) {
            unsigned long long w2[4];
#pragma unroll
            for (int fp = 0; fp < 4; fp++)
                w2[fp] = *reinterpret_cast<const unsigned long long*>(&Wsm[s][kk * 64 + f0 + 2 * fp]);
#pragma unroll
            for (int r = 0; r < 4; r++) {
                float a = Asm[s][(ty + 32 * r) * ASTR + kk];
                unsigned long long a2 = pk2(a, a);
#pragma unroll
                for (int fp = 0; fp < 4; fp++) fma2(acc[r][fp], a2, w2[fp]);
            }
        }
        __syncthreads();
        if (c + 2 < 48) issue(c + 2, s);
        CP_COMMIT();
    }

    // Epilogue: u = acc + bphi; score = dot(xf, u) / max(||u||, 1e-12)
#pragma unroll
    for (int r = 0; r < 4; r++) {
        int row = ty + 32 * r;
        int bi = row >> 6;
        float ps = 0.f, pd = 0.f;
#pragma unroll
        for (int fp = 0; fp < 4; fp++) {
            float lo, hi;
            upk2(acc[r][fp], lo, hi);
            int f = f0 + 2 * fp;
            lo += bpsm[f];
            hi += bpsm[f + 1];
            ps += lo * lo + hi * hi;
            pd += lo * xfsm[bi * 64 + f] + hi * xfsm[bi * 64 + f + 1];
        }
#pragma unroll
        for (int o = 1; o < 8; o <<= 1) {
            ps += __shfl_xor_sync(0xffffffffu, ps, o);
            pd += __shfl_xor_sync(0xffffffffu, pd, o);
        }
        if (tx == 0) g_scores[m0 + row] = pd / fmaxf(sqrtf(ps), 1e-12f);
    }
}

// ---------------- kernel C: softmax weights + switch ----------------
__global__ void __launch_bounds__(256) kernC(const float* __restrict__ sig_scale,
                                             const float* __restrict__ sig_shift) {
    int warp = threadIdx.x >> 5, lane = threadIdx.x & 31;
    int b = blockIdx.x * 8 + warp;
    float s0 = g_scores[b * 64 + lane];
    float s1 = g_scores[b * 64 + 32 + lane];
    float t0 = s0 * SHARPNESS, t1 = s1 * SHARPNESS;
    float mraw = fmaxf(s0, s1), mt = fmaxf(t0, t1);
#pragma unroll
    for (int o = 16; o >= 1; o >>= 1) {
        mraw = fmaxf(mraw, __shfl_xor_sync(0xffffffffu, mraw, o));
        mt   = fmaxf(mt,   __shfl_xor_sync(0xffffffffu, mt, o));
    }
    float e0 = expf(t0 - mt), e1 = expf(t1 - mt);
    float sum = e0 + e1;
#pragma unroll
    for (int o = 16; o >= 1; o >>= 1) sum += __shfl_xor_sync(0xffffffffu, sum, o);
    float inv = 1.f / sum;
    g_weights[b * 64 + lane]      = e0 * inv;
    g_weights[b * 64 + 32 + lane] = e1 * inv;
    if (lane == 0) {
        float z = mraw * sig_scale[0] + sig_shift[0];
        g_sw[b] = 1.f / (1.f + expf(-z));
    }
}

// ---------------- kernel D: sparse weighted sum over p + Wg/Wo mix + blend ----------------
__global__ void __launch_bounds__(192) kernD(const float* __restrict__ x,
                                             const float* __restrict__ p,
                                             const float* __restrict__ Wg,
                                             const float* __restrict__ bgv,
                                             const float* __restrict__ Wo,
                                             const float* __restrict__ bov,
                                             float* __restrict__ out) {
    __shared__ float wsm[64];
    __shared__ float buf[DIN];
    int tid = threadIdx.x;
    int b = blockIdx.x;
    if (tid < 64) wsm[tid] = g_weights[b * 64 + tid];
    __syncthreads();

    float4 acc = make_float4(0.f, 0.f, 0.f, 0.f);
    const float4* pb = (const float4*)(p + (size_t)b * KK * DIN);
    for (int k = 0; k < 64; k++) {
        float w = wsm[k];
        if (w > 1e-10f) {                      // block-uniform branch
            float4 v = pb[k * 192 + tid];
            acc.x += w * v.x; acc.y += w * v.y; acc.z += w * v.z; acc.w += w * v.w;
        }
    }
    ((float4*)buf)[tid] = acc;
    __syncthreads();

    int o = tid / 64;
    int hw = (tid % 64) * 4;
    float gg0 = Wg[o * 3 + 0], gg1 = Wg[o * 3 + 1], gg2 = Wg[o * 3 + 2];
    float bgc = bgv[o];
    float t[4];
#pragma unroll
    for (int j = 0; j < 4; j++)
        t[j] = gg0 * buf[hw + j] + gg1 * buf[256 + hw + j] + gg2 * buf[512 + hw + j] + bgc;
    __syncthreads();
#pragma unroll
    for (int j = 0; j < 4; j++) buf[o * 256 + hw + j] = t[j];
    __syncthreads();

    float oo0 = Wo[o * 3 + 0], oo1 = Wo[o * 3 + 1], oo2 = Wo[o * 3 + 2];
    float boc = bov[o];
    float sw = g_sw[b];
    float4 xv = ((const float4*)(x + (size_t)b * DIN))[tid];
    float pa0 = oo0 * buf[hw + 0] + oo1 * buf[256 + hw + 0] + oo2 * buf[512 + hw + 0] + boc;
    float pa1 = oo0 * buf[hw + 1] + oo1 * buf[256 + hw + 1] + oo2 * buf[512 + hw + 1] + boc;
    float pa2 = oo0 * buf[hw + 2] + oo1 * buf[256 + hw + 2] + oo2 * buf[512 + hw + 2] + boc;
    float pa3 = oo0 * buf[hw + 3] + oo1 * buf[256 + hw + 3] + oo2 * buf[512 + hw + 3] + boc;
    float4 ov;
    ov.x = xv.x * (1.f - sw) + pa0 * sw;
    ov.y = xv.y * (1.f - sw) + pa1 * sw;
    ov.z = xv.z * (1.f - sw) + pa2 * sw;
    ov.w = xv.w * (1.f - sw) + pa3 * sw;
    ((float4*)(out + (size_t)b * DIN))[tid] = ov;
}

// ---------------- launch ----------------
extern "C" void kernel_launch(void* const* d_in, const int* in_sizes, int n_in,
                              void* d_out, int out_size) {
    const float* x         = (const float*)d_in[0];
    const float* p         = (const float*)d_in[1];
    const float* x_im      = (const float*)d_in[2];
    const float* p_im      = (const float*)d_in[3];
    const float* Wtheta    = (const float*)d_in[4];
    const float* btheta    = (const float*)d_in[5];
    const float* Wphi      = (const float*)d_in[6];
    const float* bphi      = (const float*)d_in[7];
    const float* Wg        = (const float*)d_in[8];
    const float* bg        = (const float*)d_in[9];
    const float* Wo        = (const float*)d_in[10];
    const float* bo        = (const float*)d_in[11];
    const float* sig_scale = (const float*)d_in[12];
    const float* sig_shift = (const float*)d_in[13];
    float* out = (float*)d_out;

    kernE<<<(DIN * CF) / 256, 256>>>(Wphi);
    kernA<<<BB / 8, 256>>>(x_im, Wtheta, btheta);
    kernB<<<MROWS / 128, 256>>>(p_im, bphi);
    kernC<<<BB / 8, 256>>>(sig_scale, sig_shift);
    kernD<<<BB, 192>>>(x, p, Wg, bg, Wo, bo, out);
}

// round 2
// speedup vs baseline: 1.0159x; 1.0159x over previous
#include <cuda_runtime.h>
#include <cuda_bf16.h>
#include <math.h>

// Problem constants (fixed by the dataset)
#define BB 2048
#define KK 64
#define CC 3
#define EE 16
#define DIN 768            // C*E*E
#define CF 64
#define MROWS (BB*KK)      // 131072
#define SHARPNESS 1048576.0f   // CF * E*E*E * 4

// ---------------- scratch (no allocations allowed) ----------------
__device__ float g_WphiT[DIN*CF];       // Wphi transposed [k][f]
__device__ float g_xfeat[BB*CF];        // normalized x features
__device__ float g_scores[MROWS];       // scores[b*K+k]
__device__ float g_weights[MROWS];      // softmax weights
__device__ float g_sw[BB];              // switch per b

// ---------------- helpers ----------------
__device__ __forceinline__ void cpa16(void* smem, const void* g) {
    unsigned s = (unsigned)__cvta_generic_to_shared(smem);
    asm volatile("cp.async.cg.shared.global [%0], [%1], 16;" :: "r"(s), "l"(g));
}
#define CP_COMMIT() asm volatile("cp.async.commit_group;")
#define CP_WAIT1()  asm volatile("cp.async.wait_group 1;")

__device__ __forceinline__ unsigned long long pk2(float a, float b) {
    unsigned long long r;
    asm("mov.b64 %0, {%1, %2};" : "=l"(r) : "f"(a), "f"(b));
    return r;
}
__device__ __forceinline__ void fma2(unsigned long long& d, unsigned long long a, unsigned long long b) {
    asm("fma.rn.f32x2 %0, %1, %2, %0;" : "+l"(d) : "l"(a), "l"(b));
}
__device__ __forceinline__ void upk2(unsigned long long v, float& a, float& b) {
    asm("mov.b64 {%0, %1}, %2;" : "=f"(a), "=f"(b) : "l"(v));
}

// ---------------- kernel E: transpose Wphi [64][768] -> [768][64] ----------------
__global__ void kernE(const float* __restrict__ Wphi) {
    int o = blockIdx.x * 256 + threadIdx.x;   // o = k*64 + f
    int k = o >> 6, f = o & 63;
    g_WphiT[o] = Wphi[f * DIN + k];
}

// ---------------- kernel A: x_feat = l2norm(x_im @ Wtheta^T + btheta) ----------------
__global__ void __launch_bounds__(256) kernA(const float* __restrict__ xim,
                                             const float* __restrict__ Wtheta,
                                             const float* __restrict__ btheta) {
    __shared__ __align__(16) float xs[8 * DIN];      // 24KB
    __shared__ float wred[8][2];
    int tid = threadIdx.x;
    int b0 = blockIdx.x * 8;

    const float4* src = (const float4*)(xim + (size_t)b0 * DIN);
    float4* d4 = (float4*)xs;
#pragma unroll
    for (int j = 0; j < 6; j++) d4[tid + 256 * j] = src[tid + 256 * j];
    __syncthreads();

    int f = tid & 63, g = tid >> 6;
    const float* wr = Wtheta + (size_t)f * DIN;
    const float* xa = xs + (2 * g) * DIN;
    const float* xb = xs + (2 * g + 1) * DIN;
    float a0 = 0.f, a1 = 0.f;
    for (int i = 0; i < DIN; i += 4) {
        float4 w4 = *(const float4*)(wr + i);
        float4 va = *(const float4*)(xa + i);
        float4 vb = *(const float4*)(xb + i);
        a0 += w4.x * va.x + w4.y * va.y + w4.z * va.z + w4.w * va.w;
        a1 += w4.x * vb.x + w4.y * vb.y + w4.z * vb.z + w4.w * vb.w;
    }
    a0 += btheta[f];
    a1 += btheta[f];

    float s0 = a0 * a0, s1 = a1 * a1;
#pragma unroll
    for (int o = 1; o < 32; o <<= 1) {
        s0 += __shfl_xor_sync(0xffffffffu, s0, o);
        s1 += __shfl_xor_sync(0xffffffffu, s1, o);
    }
    int w = tid >> 5;
    if ((tid & 31) == 0) { wred[w][0] = s0; wred[w][1] = s1; }
    __syncthreads();
    int wb = g << 1;
    float n0 = wred[wb][0] + wred[wb + 1][0];
    float n1 = wred[wb][1] + wred[wb + 1][1];
    g_xfeat[(b0 + 2 * g) * CF + f]     = a0 / fmaxf(sqrtf(n0), 1e-12f);
    g_xfeat[(b0 + 2 * g + 1) * CF + f] = a1 / fmaxf(sqrtf(n1), 1e-12f);
}

// ---------------- kernel B: scores GEMM (the big one) ----------------
// Tile: 128 rows x 64 feats, k-chunk 16, 3-stage cp.async ring, ONE sync/chunk.
// Thread (ty=tid>>3, tx=tid&7): rows ty+32r (r=0..3), feats 8*tx..8*tx+7.
// LDS diet: W via 2x LDS.128/kk, A via LDS.64 kk-pairs (4 LDS per kk total).
#define ASTR 20     // A smem row stride (floats): 16B cp.async alignment, 8B LDS.64 alignment
#define NSTG 3
__global__ void __launch_bounds__(256) kernB(const float* __restrict__ pim,
                                             const float* __restrict__ bphi) {
    __shared__ __align__(16) float Asm[NSTG][128 * ASTR];   // 30.7KB
    __shared__ __align__(16) float Wsm[NSTG][16 * 64];      // 12.3KB
    __shared__ float xfsm[128];
    __shared__ float bpsm[64];

    const int tid = threadIdx.x;
    const int m0 = blockIdx.x * 128;
    if (tid < 128) xfsm[tid] = g_xfeat[m0 + tid];
    if (tid < 64)  bpsm[tid] = bphi[tid];

    const int ty = tid >> 3, tx = tid & 7, f0 = tx * 8;
    unsigned long long acc[4][4];
#pragma unroll
    for (int r = 0; r < 4; r++)
#pragma unroll
        for (int fp = 0; fp < 4; fp++) acc[r][fp] = 0ull;

    const int arow = tid >> 2;
    const int aseg = (tid & 3) * 4;
    const int wk   = tid >> 4;
    const int wf4  = (tid & 15) * 4;

    auto issue = [&](int c, int s) {
#pragma unroll
        for (int j = 0; j < 2; j++) {
            int row = arow + 64 * j;
            cpa16(&Asm[s][row * ASTR + aseg],
                  pim + (size_t)(m0 + row) * DIN + c * 16 + aseg);
        }
        cpa16(&Wsm[s][wk * 64 + wf4], g_WphiT + (size_t)(c * 16 + wk) * 64 + wf4);
    };

    issue(0, 0); CP_COMMIT();
    issue(1, 1); CP_COMMIT();

    for (int c = 0; c < 48; c++) {
        const int s = c % NSTG;
        CP_WAIT1();
        __syncthreads();          // stage s visible to all; all done reading stage (c+2)%NSTG from iter c-1
        if (c + 2 < 48) issue(c + 2, (c + 2) % NSTG);
        CP_COMMIT();

#pragma unroll
        for (int kp = 0; kp < 8; kp++) {       // kk pairs
            // A: one LDS.64 per row gives (a_k, a_k+1)
            float2 av[4];
#pragma unroll
            for (int r = 0; r < 4; r++)
                av[r] = *reinterpret_cast<const float2*>(&Asm[s][(ty + 32 * r) * ASTR + kp * 2]);

#pragma unroll
            for (int h = 0; h < 2; h++) {      // two kk within the pair
                const int kk = kp * 2 + h;
                // W: 2x LDS.128 -> 4 f32x2 operands
                float4 wv0 = *reinterpret_cast<const float4*>(&Wsm[s][kk * 64 + f0]);
                float4 wv1 = *reinterpret_cast<const float4*>(&Wsm[s][kk * 64 + f0 + 4]);
                unsigned long long w2[4];
                w2[0] = pk2(wv0.x, wv0.y);
                w2[1] = pk2(wv0.z, wv0.w);
                w2[2] = pk2(wv1.x, wv1.y);
                w2[3] = pk2(wv1.z, wv1.w);
#pragma unroll
                for (int r = 0; r < 4; r++) {
                    float a = h ? av[r].y : av[r].x;
                    unsigned long long a2 = pk2(a, a);
#pragma unroll
                    for (int fp = 0; fp < 4; fp++) fma2(acc[r][fp], a2, w2[fp]);
                }
            }
        }
    }

    // Epilogue: u = acc + bphi; score = dot(xf, u) / max(||u||, 1e-12)
#pragma unroll
    for (int r = 0; r < 4; r++) {
        int row = ty + 32 * r;
        int bi = row >> 6;
        float ps = 0.f, pd = 0.f;
#pragma unroll
        for (int fp = 0; fp < 4; fp++) {
            float lo, hi;
            upk2(acc[r][fp], lo, hi);
            int f = f0 + 2 * fp;
            lo += bpsm[f];
            hi += bpsm[f + 1];
            ps += lo * lo + hi * hi;
            pd += lo * xfsm[bi * 64 + f] + hi * xfsm[bi * 64 + f + 1];
        }
#pragma unroll
        for (int o = 1; o < 8; o <<= 1) {
            ps += __shfl_xor_sync(0xffffffffu, ps, o);
            pd += __shfl_xor_sync(0xffffffffu, pd, o);
        }
        if (tx == 0) g_scores[m0 + row] = pd / fmaxf(sqrtf(ps), 1e-12f);
    }
}

// ---------------- kernel C: softmax weights + switch ----------------
__global__ void __launch_bounds__(256) kernC(const float* __restrict__ sig_scale,
                                             const float* __restrict__ sig_shift) {
    int warp = threadIdx.x >> 5, lane = threadIdx.x & 31;
    int b = blockIdx.x * 8 + warp;
    float s0 = g_scores[b * 64 + lane];
    float s1 = g_scores[b * 64 + 32 + lane];
    float t0 = s0 * SHARPNESS, t1 = s1 * SHARPNESS;
    float mraw = fmaxf(s0, s1), mt = fmaxf(t0, t1);
#pragma unroll
    for (int o = 16; o >= 1; o >>= 1) {
        mraw = fmaxf(mraw, __shfl_xor_sync(0xffffffffu, mraw, o));
        mt   = fmaxf(mt,   __shfl_xor_sync(0xffffffffu, mt, o));
    }
    float e0 = expf(t0 - mt), e1 = expf(t1 - mt);
    float sum = e0 + e1;
#pragma unroll
    for (int o = 16; o >= 1; o >>= 1) sum += __shfl_xor_sync(0xffffffffu, sum, o);
    float inv = 1.f / sum;
    g_weights[b * 64 + lane]      = e0 * inv;
    g_weights[b * 64 + 32 + lane] = e1 * inv;
    if (lane == 0) {
        float z = mraw * sig_scale[0] + sig_shift[0];
        g_sw[b] = 1.f / (1.f + expf(-z));
    }
}

// ---------------- kernel D: sparse weighted sum over p + Wg/Wo mix + blend ----------------
__global__ void __launch_bounds__(192) kernD(const float* __restrict__ x,
                                             const float* __restrict__ p,
                                             const float* __restrict__ Wg,
                                             const float* __restrict__ bgv,
                                             const float* __restrict__ Wo,
                                             const float* __restrict__ bov,
                                             float* __restrict__ out) {
    __shared__ float wsm[64];
    __shared__ float buf[DIN];
    int tid = threadIdx.x;
    int b = blockIdx.x;
    if (tid < 64) wsm[tid] = g_weights[b * 64 + tid];
    __syncthreads();

    float4 acc = make_float4(0.f, 0.f, 0.f, 0.f);
    const float4* pb = (const float4*)(p + (size_t)b * KK * DIN);
    for (int k = 0; k < 64; k++) {
        float w = wsm[k];
        if (w > 1e-10f) {                      // block-uniform branch
            float4 v = pb[k * 192 + tid];
            acc.x += w * v.x; acc.y += w * v.y; acc.z += w * v.z; acc.w += w * v.w;
        }
    }
    ((float4*)buf)[tid] = acc;
    __syncthreads();

    int o = tid / 64;
    int hw = (tid % 64) * 4;
    float gg0 = Wg[o * 3 + 0], gg1 = Wg[o * 3 + 1], gg2 = Wg[o * 3 + 2];
    float bgc = bgv[o];
    float t[4];
#pragma unroll
    for (int j = 0; j < 4; j++)
        t[j] = gg0 * buf[hw + j] + gg1 * buf[256 + hw + j] + gg2 * buf[512 + hw + j] + bgc;
    __syncthreads();
#pragma unroll
    for (int j = 0; j < 4; j++) buf[o * 256 + hw + j] = t[j];
    __syncthreads();

    float oo0 = Wo[o * 3 + 0], oo1 = Wo[o * 3 + 1], oo2 = Wo[o * 3 + 2];
    float boc = bov[o];
    float sw = g_sw[b];
    float4 xv = ((const float4*)(x + (size_t)b * DIN))[tid];
    float pa0 = oo0 * buf[hw + 0] + oo1 * buf[256 + hw + 0] + oo2 * buf[512 + hw + 0] + boc;
    float pa1 = oo0 * buf[hw + 1] + oo1 * buf[256 + hw + 1] + oo2 * buf[512 + hw + 1] + boc;
    float pa2 = oo0 * buf[hw + 2] + oo1 * buf[256 + hw + 2] + oo2 * buf[512 + hw + 2] + boc;
    float pa3 = oo0 * buf[hw + 3] + oo1 * buf[256 + hw + 3] + oo2 * buf[512 + hw + 3] + boc;
    float4 ov;
    ov.x = xv.x * (1.f - sw) + pa0 * sw;
    ov.y = xv.y * (1.f - sw) + pa1 * sw;
    ov.z = xv.z * (1.f - sw) + pa2 * sw;
    ov.w = xv.w * (1.f - sw) + pa3 * sw;
    ((float4*)(out + (size_t)b * DIN))[tid] = ov;
}

// ---------------- launch ----------------
extern "C" void kernel_launch(void* const* d_in, const int* in_sizes, int n_in,
                              void* d_out, int out_size) {
    const float* x         = (const float*)d_in[0];
    const float* p         = (const float*)d_in[1];
    const float* x_im      = (const float*)d_in[2];
    const float* p_im      = (const float*)d_in[3];
    const float* Wtheta    = (const float*)d_in[4];
    const float* btheta    = (const float*)d_in[5];
    const float* Wphi      = (const float*)d_in[6];
    const float* bphi      = (const float*)d_in[7];
    const float* Wg        = (const float*)d_in[8];
    const float* bg        = (const float*)d_in[9];
    const float* Wo        = (const float*)d_in[10];
    const float* bo        = (const float*)d_in[11];
    const float* sig_scale = (const float*)d_in[12];
    const float* sig_shift = (const float*)d_in[13];
    float* out = (float*)d_out;

    kernE<<<(DIN * CF) / 256, 256>>>(Wphi);
    kernA<<<BB / 8, 256>>>(x_im, Wtheta, btheta);
    kernB<<<MROWS / 128, 256>>>(p_im, bphi);
    kernC<<<BB / 8, 256>>>(sig_scale, sig_shift);
    kernD<<<BB, 192>>>(x, p, Wg, bg, Wo, bo, out);
}

// round 4
// speedup vs baseline: 2.4885x; 2.4495x over previous
#include <cuda_runtime.h>
#include <cuda_bf16.h>
#include <math.h>
#include <stdint.h>

// Problem constants
#define BB 2048
#define KK 64
#define DIN 768
#define CF 64
#define MROWS (BB*KK)
#define SHARPNESS 1048576.0f
#define NCH 12            // K chunks of 64

// ---------------- scratch ----------------
__device__ float g_xfeat[BB*CF];
__device__ float g_scores[MROWS];
__device__ float g_weights[MROWS];
__device__ float g_sw[BB];
// Fragment-ordered bf16 hi/lo images of Wphi: [chunk][hilo][ks][nt][lane] uint2
__device__ __align__(16) uint2 g_Bfrag[NCH*2*4*8*32];   // 196KB, L2-resident

// ---------------- helpers ----------------
__device__ __forceinline__ void cpa16(void* smem, const void* g) {
    unsigned s = (unsigned)__cvta_generic_to_shared(smem);
    asm volatile("cp.async.cg.shared.global [%0], [%1], 16;" :: "r"(s), "l"(g));
}
#define CP_COMMIT() asm volatile("cp.async.commit_group;")
#define CP_WAIT1()  asm volatile("cp.async.wait_group 1;" ::: "memory")

__device__ __forceinline__ void cvt_split(float a0, float a1, uint32_t& hp, uint32_t& lp) {
    // pack {lo16=a0, hi16=a1} as bf16x2; lp = residuals
    asm("cvt.rn.satfinite.bf16x2.f32 %0, %1, %2;" : "=r"(hp) : "f"(a1), "f"(a0));
    float h0 = __uint_as_float(hp << 16);
    float h1 = __uint_as_float(hp & 0xffff0000u);
    float l0 = a0 - h0, l1 = a1 - h1;
    asm("cvt.rn.satfinite.bf16x2.f32 %0, %1, %2;" : "=r"(lp) : "f"(l1), "f"(l0));
}

__device__ __forceinline__ void mma_bf16(float* d, const uint32_t* a, uint32_t b0, uint32_t b1) {
    asm volatile("mma.sync.aligned.m16n8k16.row.col.f32.bf16.bf16.f32 "
        "{%0,%1,%2,%3}, {%4,%5,%6,%7}, {%8,%9}, {%0,%1,%2,%3};"
        : "+f"(d[0]), "+f"(d[1]), "+f"(d[2]), "+f"(d[3])
        : "r"(a[0]), "r"(a[1]), "r"(a[2]), "r"(a[3]), "r"(b0), "r"(b1));
}

// ---------------- kernel E: Wphi -> fragment-ordered bf16 hi/lo ----------------
// idx -> (c, ks, nt, lane); values: Wphi[n=nt*8+g][k0+2tig + {0,1,8,9}]
__global__ void kernE(const float* __restrict__ Wphi) {
    int idx = blockIdx.x * 256 + threadIdx.x;    // < 12288
    int lane = idx & 31;
    int t = idx >> 5;                            // c*32 + ks*8 + nt
    int nt = t & 7, ks = (t >> 3) & 3, c = t >> 5;
    int g = lane >> 2, tig = lane & 3;
    int n = nt * 8 + g;
    int k0 = c * 64 + ks * 16 + 2 * tig;
    const float* wr = Wphi + n * DIN + k0;
    float w0 = wr[0], w1 = wr[1], w2 = wr[8], w3 = wr[9];
    uint32_t h01, l01, h23, l23;
    cvt_split(w0, w1, h01, l01);
    cvt_split(w2, w3, h23, l23);
    int base = ((c * 2 + 0) * 4 + ks) * 256 + nt * 32 + lane;
    g_Bfrag[base]        = make_uint2(h01, h23);
    g_Bfrag[base + 1024] = make_uint2(l01, l23);   // hilo=1 plane
}

// ---------------- kernel A: x_feat = l2norm(x_im @ Wtheta^T + btheta) ----------------
__global__ void __launch_bounds__(256) kernA(const float* __restrict__ xim,
                                             const float* __restrict__ Wtheta,
                                             const float* __restrict__ btheta) {
    __shared__ __align__(16) float xs[8 * DIN];
    __shared__ float wred[8][2];
    int tid = threadIdx.x;
    int b0 = blockIdx.x * 8;
    const float4* src = (const float4*)(xim + (size_t)b0 * DIN);
    float4* d4 = (float4*)xs;
#pragma unroll
    for (int j = 0; j < 6; j++) d4[tid + 256 * j] = src[tid + 256 * j];
    __syncthreads();
    int f = tid & 63, g = tid >> 6;
    const float* wr = Wtheta + (size_t)f * DIN;
    const float* xa = xs + (2 * g) * DIN;
    const float* xb = xs + (2 * g + 1) * DIN;
    float a0 = 0.f, a1 = 0.f;
    for (int i = 0; i < DIN; i += 4) {
        float4 w4 = *(const float4*)(wr + i);
        float4 va = *(const float4*)(xa + i);
        float4 vb = *(const float4*)(xb + i);
        a0 += w4.x * va.x + w4.y * va.y + w4.z * va.z + w4.w * va.w;
        a1 += w4.x * vb.x + w4.y * vb.y + w4.z * vb.z + w4.w * vb.w;
    }
    a0 += btheta[f]; a1 += btheta[f];
    float s0 = a0 * a0, s1 = a1 * a1;
#pragma unroll
    for (int o = 1; o < 32; o <<= 1) {
        s0 += __shfl_xor_sync(0xffffffffu, s0, o);
        s1 += __shfl_xor_sync(0xffffffffu, s1, o);
    }
    int w = tid >> 5;
    if ((tid & 31) == 0) { wred[w][0] = s0; wred[w][1] = s1; }
    __syncthreads();
    int wb = g << 1;
    float n0 = wred[wb][0] + wred[wb + 1][0];
    float n1 = wred[wb][1] + wred[wb + 1][1];
    g_xfeat[(b0 + 2 * g) * CF + f]     = a0 / fmaxf(sqrtf(n0), 1e-12f);
    g_xfeat[(b0 + 2 * g + 1) * CF + f] = a1 / fmaxf(sqrtf(n1), 1e-12f);
}

// ---------------- kernel B: HMMA bf16 split-3 GEMM + fused score epilogue ----------------
__device__ __forceinline__ void computeChunk(const float2* Abuf, const uint2* Bst,
                                             float acc[8][4], int lane) {
#pragma unroll
    for (int ks = 0; ks < 4; ks++) {
        uint32_t Ah[4], Al[4];
#pragma unroll
        for (int i = 0; i < 4; i++)
            cvt_split(Abuf[ks * 4 + i].x, Abuf[ks * 4 + i].y, Ah[i], Al[i]);
#pragma unroll
        for (int nt = 0; nt < 8; nt++) {
            uint2 bh = Bst[(ks * 8 + nt) * 32 + lane];
            uint2 bl = Bst[1024 + (ks * 8 + nt) * 32 + lane];
            mma_bf16(acc[nt], Ah, bh.x, bh.y);   // hi*hi
            mma_bf16(acc[nt], Al, bh.x, bh.y);   // lo*hi
            mma_bf16(acc[nt], Ah, bl.x, bl.y);   // hi*lo
        }
    }
}

__global__ void __launch_bounds__(256, 2) kernB(const float* __restrict__ pim,
                                                const float* __restrict__ bphi) {
    __shared__ __align__(16) uint2 Bsm[2][2048];   // 2 stages x 16KB
    __shared__ float xfsm[128];
    __shared__ float bpsm[64];

    int tid = threadIdx.x, w = tid >> 5, lane = tid & 31;
    int g = lane >> 2, tig = lane & 3;
    int m0 = blockIdx.x * 128;
    if (tid < 128) xfsm[tid] = g_xfeat[m0 + tid];
    else if (tid < 192) bpsm[tid - 128] = bphi[tid - 128];

    const float* abase = pim + (size_t)(m0 + 16 * w + g) * DIN + 2 * tig;

    float acc[8][4];
#pragma unroll
    for (int nt = 0; nt < 8; nt++)
#pragma unroll
        for (int i = 0; i < 4; i++) acc[nt][i] = 0.f;

    float2 A0[16], A1[16];

    auto ldB = [&](int c, int s) {
        const char* src = (const char*)g_Bfrag + (size_t)c * 16384 + tid * 64;
        char* dst = (char*)&Bsm[s][0] + tid * 64;
        cpa16(dst, src); cpa16(dst + 16, src + 16);
        cpa16(dst + 32, src + 32); cpa16(dst + 48, src + 48);
        CP_COMMIT();
    };
    auto ldA = [&](int c, float2* buf) {
#pragma unroll
        for (int ks = 0; ks < 4; ks++) {
            const float* pp = abase + c * 64 + ks * 16;
            buf[ks * 4 + 0] = *(const float2*)(pp);
            buf[ks * 4 + 1] = *(const float2*)(pp + 8 * DIN);
            buf[ks * 4 + 2] = *(const float2*)(pp + 8);
            buf[ks * 4 + 3] = *(const float2*)(pp + 8 * DIN + 8);
        }
    };

    ldB(0, 0); ldB(1, 1);
    ldA(0, A0);

#pragma unroll
    for (int cc = 0; cc < 6; cc++) {
        {   // even chunk, stage 0
            const int c = 2 * cc;
            if (c + 1 < NCH) ldA(c + 1, A1);
            CP_WAIT1(); __syncthreads();
            computeChunk(A0, &Bsm[0][0], acc, lane);
            __syncthreads();
            if (c + 2 < NCH) ldB(c + 2, 0); else CP_COMMIT();
        }
        {   // odd chunk, stage 1
            const int c = 2 * cc + 1;
            if (c + 1 < NCH) ldA(c + 1, A0);
            CP_WAIT1(); __syncthreads();
            computeChunk(A1, &Bsm[1][0], acc, lane);
            __syncthreads();
            if (c + 2 < NCH) ldB(c + 2, 1); else CP_COMMIT();
        }
    }

    // Epilogue: u = D + bphi; score = dot(xf,u)/max(||u||,1e-12)
    int bi = w >> 2;
    float ps0 = 0.f, pd0 = 0.f, ps1 = 0.f, pd1 = 0.f;
#pragma unroll
    for (int nt = 0; nt < 8; nt++) {
        int col = nt * 8 + 2 * tig;
        float b0 = bpsm[col], b1 = bpsm[col + 1];
        float x0 = xfsm[bi * 64 + col], x1 = xfsm[bi * 64 + col + 1];
        float u;
        u = acc[nt][0] + b0; ps0 += u * u; pd0 += u * x0;
        u = acc[nt][1] + b1; ps0 += u * u; pd0 += u * x1;
        u = acc[nt][2] + b0; ps1 += u * u; pd1 += u * x0;
        u = acc[nt][3] + b1; ps1 += u * u; pd1 += u * x1;
    }
#pragma unroll
    for (int o = 1; o < 4; o <<= 1) {
        ps0 += __shfl_xor_sync(0xffffffffu, ps0, o);
        pd0 += __shfl_xor_sync(0xffffffffu, pd0, o);
        ps1 += __shfl_xor_sync(0xffffffffu, ps1, o);
        pd1 += __shfl_xor_sync(0xffffffffu, pd1, o);
    }
    if (tig == 0) {
        int r = m0 + 16 * w + g;
        g_scores[r]     = pd0 / fmaxf(sqrtf(ps0), 1e-12f);
        g_scores[r + 8] = pd1 / fmaxf(sqrtf(ps1), 1e-12f);
    }
}

// ---------------- kernel C: softmax weights + switch ----------------
__global__ void __launch_bounds__(256) kernC(const float* __restrict__ sig_scale,
                                             const float* __restrict__ sig_shift) {
    int warp = threadIdx.x >> 5, lane = threadIdx.x & 31;
    int b = blockIdx.x * 8 + warp;
    float s0 = g_scores[b * 64 + lane];
    float s1 = g_scores[b * 64 + 32 + lane];
    float t0 = s0 * SHARPNESS, t1 = s1 * SHARPNESS;
    float mraw = fmaxf(s0, s1), mt = fmaxf(t0, t1);
#pragma unroll
    for (int o = 16; o >= 1; o >>= 1) {
        mraw = fmaxf(mraw, __shfl_xor_sync(0xffffffffu, mraw, o));
        mt   = fmaxf(mt,   __shfl_xor_sync(0xffffffffu, mt, o));
    }
    float e0 = expf(t0 - mt), e1 = expf(t1 - mt);
    float sum = e0 + e1;
#pragma unroll
    for (int o = 16; o >= 1; o >>= 1) sum += __shfl_xor_sync(0xffffffffu, sum, o);
    float inv = 1.f / sum;
    g_weights[b * 64 + lane]      = e0 * inv;
    g_weights[b * 64 + 32 + lane] = e1 * inv;
    if (lane == 0) {
        float z = mraw * sig_scale[0] + sig_shift[0];
        g_sw[b] = 1.f / (1.f + expf(-z));
    }
}

// ---------------- kernel D: sparse weighted sum + Wg/Wo mix + blend ----------------
__global__ void __launch_bounds__(192) kernD(const float* __restrict__ x,
                                             const float* __restrict__ p,
                                             const float* __restrict__ Wg,
                                             const float* __restrict__ bgv,
                                             const float* __restrict__ Wo,
                                             const float* __restrict__ bov,
                                             float* __restrict__ out) {
    __shared__ float wsm[64];
    __shared__ float buf[DIN];
    int tid = threadIdx.x;
    int b = blockIdx.x;
    if (tid < 64) wsm[tid] = g_weights[b * 64 + tid];
    __syncthreads();

    float4 acc = make_float4(0.f, 0.f, 0.f, 0.f);
    const float4* pb = (const float4*)(p + (size_t)b * KK * DIN);
    for (int k = 0; k < 64; k++) {
        float w = wsm[k];
        if (w > 1e-10f) {
            float4 v = pb[k * 192 + tid];
            acc.x += w * v.x; acc.y += w * v.y; acc.z += w * v.z; acc.w += w * v.w;
        }
    }
    ((float4*)buf)[tid] = acc;
    __syncthreads();

    int o = tid / 64;
    int hw = (tid % 64) * 4;
    float gg0 = Wg[o * 3 + 0], gg1 = Wg[o * 3 + 1], gg2 = Wg[o * 3 + 2];
    float bgc = bgv[o];
    float t[4];
#pragma unroll
    for (int j = 0; j < 4; j++)
        t[j] = gg0 * buf[hw + j] + gg1 * buf[256 + hw + j] + gg2 * buf[512 + hw + j] + bgc;
    __syncthreads();
#pragma unroll
    for (int j = 0; j < 4; j++) buf[o * 256 + hw + j] = t[j];
    __syncthreads();

    float oo0 = Wo[o * 3 + 0], oo1 = Wo[o * 3 + 1], oo2 = Wo[o * 3 + 2];
    float boc = bov[o];
    float sw = g_sw[b];
    float4 xv = ((const float4*)(x + (size_t)b * DIN))[tid];
    float pa0 = oo0 * buf[hw + 0] + oo1 * buf[256 + hw + 0] + oo2 * buf[512 + hw + 0] + boc;
    float pa1 = oo0 * buf[hw + 1] + oo1 * buf[256 + hw + 1] + oo2 * buf[512 + hw + 1] + boc;
    float pa2 = oo0 * buf[hw + 2] + oo1 * buf[256 + hw + 2] + oo2 * buf[512 + hw + 2] + boc;
    float pa3 = oo0 * buf[hw + 3] + oo1 * buf[256 + hw + 3] + oo2 * buf[512 + hw + 3] + boc;
    float4 ov;
    ov.x = xv.x * (1.f - sw) + pa0 * sw;
    ov.y = xv.y * (1.f - sw) + pa1 * sw;
    ov.z = xv.z * (1.f - sw) + pa2 * sw;
    ov.w = xv.w * (1.f - sw) + pa3 * sw;
    ((float4*)(out + (size_t)b * DIN))[tid] = ov;
}

// ---------------- launch ----------------
extern "C" void kernel_launch(void* const* d_in, const int* in_sizes, int n_in,
                              void* d_out, int out_size) {
    const float* x         = (const float*)d_in[0];
    const float* p         = (const float*)d_in[1];
    const float* x_im      = (const float*)d_in[2];
    const float* p_im      = (const float*)d_in[3];
    const float* Wtheta    = (const float*)d_in[4];
    const float* btheta    = (const float*)d_in[5];
    const float* Wphi      = (const float*)d_in[6];
    const float* bphi      = (const float*)d_in[7];
    const float* Wg        = (const float*)d_in[8];
    const float* bg        = (const float*)d_in[9];
    const float* Wo        = (const float*)d_in[10];
    const float* bo        = (const float*)d_in[11];
    const float* sig_scale = (const float*)d_in[12];
    const float* sig_shift = (const float*)d_in[13];
    float* out = (float*)d_out;

    kernE<<<48, 256>>>(Wphi);
    kernA<<<BB / 8, 256>>>(x_im, Wtheta, btheta);
    kernB<<<MROWS / 128, 256>>>(p_im, bphi);
    kernC<<<BB / 8, 256>>>(sig_scale, sig_shift);
    kernD<<<BB, 192>>>(x, p, Wg, bg, Wo, bo, out);
}